// round 1
// baseline (speedup 1.0000x reference)
#include <cuda_runtime.h>
#include <cuda_bf16.h>

// FastFood random features: per-row (D=64) pipeline
//   v = x * c * B;  v = FWHT64(v);  v = v[P] * G;  v = FWHT64(v);  v = v * S
// with c = sqrt(1/sqrt(64)) * sqrt(1/64).
//
// Layout: one warp per row; thread 'lane' holds elements (2*lane, 2*lane+1)
// as a float2 -> coalesced LDG.64 / STG.64. FWHT bit-0 butterfly is
// register-local; bits 1..5 are shfl_xor butterflies. Permutation is a
// 4-shfl arbitrary-lane gather. B/G/S/P are register-resident per warp.

#ifndef RPT
#define RPT 4   // rows per warp per grid-stride iteration (MLP)
#endif

__global__ __launch_bounds__(256) void fastfood_kernel(
    const float* __restrict__ x,
    const float* __restrict__ B,
    const float* __restrict__ G,
    const float* __restrict__ S,
    const int*   __restrict__ P,
    float* __restrict__ out,
    int nrows)
{
    const int lane    = threadIdx.x & 31;
    const int warp_id = (blockIdx.x * blockDim.x + threadIdx.x) >> 5;
    const int nwarps  = (gridDim.x * blockDim.x) >> 5;

    const int j0 = 2 * lane;
    const int j1 = j0 + 1;

    // combined scalar: sqrt(0.125) / 8
    const float c = 0.04419417382415922f;

    // per-warp register-resident parameters
    const float b0 = __ldg(&B[j0]) * c;
    const float b1 = __ldg(&B[j1]) * c;
    const float g0 = __ldg(&G[j0]);
    const float g1 = __ldg(&G[j1]);
    const float s0 = __ldg(&S[j0]);
    const float s1 = __ldg(&S[j1]);
    const int   p0 = __ldg(&P[j0]);
    const int   p1 = __ldg(&P[j1]);

    const int p0lane = p0 >> 1, p0odd = p0 & 1;
    const int p1lane = p1 >> 1, p1odd = p1 & 1;

    const float2* __restrict__ xin  = (const float2*)x;
    float2* __restrict__       yout = (float2*)out;

    for (int base = warp_id * RPT; base < nrows; base += nwarps * RPT) {
        float v0[RPT], v1[RPT];

        // ---- loads (streaming, independent -> MLP) ----
        #pragma unroll
        for (int k = 0; k < RPT; k++) {
            int r = base + k;
            if (r < nrows) {
                float2 xv = __ldcs(&xin[(size_t)r * 32 + lane]);
                v0[k] = xv.x * b0;
                v1[k] = xv.y * b1;
            } else {
                v0[k] = 0.f; v1[k] = 0.f;
            }
        }

        // ---- FWHT #1 ----
        #pragma unroll
        for (int k = 0; k < RPT; k++) {
            // bit 0 (h=1): register-local
            float a = v0[k] + v1[k];
            float d = v0[k] - v1[k];
            v0[k] = a; v1[k] = d;
        }
        #pragma unroll
        for (int m = 1; m <= 16; m <<= 1) {
            #pragma unroll
            for (int k = 0; k < RPT; k++) {
                float o0 = __shfl_xor_sync(0xffffffffu, v0[k], m);
                float o1 = __shfl_xor_sync(0xffffffffu, v1[k], m);
                if (lane & m) { v0[k] = o0 - v0[k]; v1[k] = o1 - v1[k]; }
                else          { v0[k] = v0[k] + o0; v1[k] = v1[k] + o1; }
            }
        }

        // ---- permutation gather: new[j] = old[P[j]], then * G ----
        #pragma unroll
        for (int k = 0; k < RPT; k++) {
            float t00 = __shfl_sync(0xffffffffu, v0[k], p0lane);
            float t01 = __shfl_sync(0xffffffffu, v1[k], p0lane);
            float t10 = __shfl_sync(0xffffffffu, v0[k], p1lane);
            float t11 = __shfl_sync(0xffffffffu, v1[k], p1lane);
            float n0 = p0odd ? t01 : t00;
            float n1 = p1odd ? t11 : t10;
            v0[k] = n0 * g0;
            v1[k] = n1 * g1;
        }

        // ---- FWHT #2 ----
        #pragma unroll
        for (int k = 0; k < RPT; k++) {
            float a = v0[k] + v1[k];
            float d = v0[k] - v1[k];
            v0[k] = a; v1[k] = d;
        }
        #pragma unroll
        for (int m = 1; m <= 16; m <<= 1) {
            #pragma unroll
            for (int k = 0; k < RPT; k++) {
                float o0 = __shfl_xor_sync(0xffffffffu, v0[k], m);
                float o1 = __shfl_xor_sync(0xffffffffu, v1[k], m);
                if (lane & m) { v0[k] = o0 - v0[k]; v1[k] = o1 - v1[k]; }
                else          { v0[k] = v0[k] + o0; v1[k] = v1[k] + o1; }
            }
        }

        // ---- scale by S, store (streaming) ----
        #pragma unroll
        for (int k = 0; k < RPT; k++) {
            int r = base + k;
            if (r < nrows) {
                float2 o;
                o.x = v0[k] * s0;
                o.y = v1[k] * s1;
                __stcs(&yout[(size_t)r * 32 + lane], o);
            }
        }
    }
}

extern "C" void kernel_launch(void* const* d_in, const int* in_sizes, int n_in,
                              void* d_out, int out_size)
{
    const float* x = (const float*)d_in[0];
    const float* B = (const float*)d_in[1];
    const float* G = (const float*)d_in[2];
    const float* S = (const float*)d_in[3];
    const int*   P = (const int*)d_in[4];
    float* out = (float*)d_out;

    int nrows = in_sizes[0] / 64;   // 524288

    // 148 SMs; 256 threads/block -> 8 warps/block. Enough blocks for full
    // occupancy with a grid-stride loop amortizing the B/G/S/P loads.
    int threads = 256;
    int blocks  = 1480;

    fastfood_kernel<<<blocks, threads>>>(x, B, G, S, P, out, nrows);
}